// round 7
// baseline (speedup 1.0000x reference)
#include <cuda_runtime.h>
#include <cstdint>

typedef unsigned long long u64;
typedef unsigned int u32;

#define NUM_BITS 16
#define THETA 8
#define HN 4096
#define FF 128
#define CC 10
#define BB 64
#define P0 2048                      // F*NUM_BITS
#define SEGS_PER_LAYER (2 * HN)      // 8192
#define TOT_SEGS (3 * SEGS_PER_LAYER)
#define MAXH 32

#define OUT_BLOCKS 192
#define LH_TOTAL (3 * HN)                      // 12288
#define LH_PER_BLOCK (LH_TOTAL / OUT_BLOCKS)   // 64

// Extract kernel geometry: 2048 ull2 elements per block (256 thr x 8).
#define B_W0 2048      // 4096*2*2048 floats / 4 / 2048
#define B_W1 4096
#define B_W2 4096

// Scratch (device globals: no allocation allowed in kernel_launch)
__device__ u64 g_act[P0];                 // layer-0 input masks
__device__ u64 g_fired[3 * HN];           // per-layer fired masks
__device__ u32 g_cnt[TOT_SEGS];           // hits per segment
__device__ u32 g_hits[TOT_SEGS * MAXH];   // p | signbit<<31
__device__ float g_part[OUT_BLOCKS * BB * CC];

// -------------------------------------------------------------------------
__global__ void zero_cnt_kernel() {
    int i = blockIdx.x * blockDim.x + threadIdx.x;
    if (i < TOT_SEGS) g_cnt[i] = 0u;
}

// -------------------------------------------------------------------------
// Encode: x[B,F] -> g_act[p], p = f*16 + t, bit b = (x[b,f] >= (t+1)/17)
// -------------------------------------------------------------------------
__global__ void encode_kernel(const float* __restrict__ x) {
    int p = blockIdx.x * blockDim.x + threadIdx.x;
    if (p >= P0) return;
    int f = p >> 4;
    int t = p & 15;
    float thr = (float)(t + 1) * (1.0f / (float)(NUM_BITS + 1));
    u64 m = 0ull;
#pragma unroll
    for (int b = 0; b < BB; b++) {
        float v = __ldg(&x[b * FF + f]);
        m |= ((u64)(v >= thr)) << b;
    }
    g_act[p] = m;
}

// -------------------------------------------------------------------------
// Extract: pure stream over all three weight arrays; emit (p, sign) per
// nonzero into per-segment hit lists. Weight layout [h][s][p] row-major, so
// flat float index fidx = seg*P + p with seg = h*2+s.
// -------------------------------------------------------------------------
__device__ __forceinline__ void emit_hit(int segoff, int shift, int fidx,
                                         u32 wb) {
    int seg = segoff + (fidx >> shift);
    int p = fidx & ((1 << shift) - 1);
    u32 slot = atomicAdd(&g_cnt[seg], 1u);
    if (slot < MAXH)
        g_hits[seg * MAXH + slot] = (u32)p | (wb & 0x80000000u);
}

__global__ __launch_bounds__(256) void extract_kernel(
    const float* __restrict__ W0,
    const float* __restrict__ W1,
    const float* __restrict__ W2) {
    int b = blockIdx.x;
    const float* W;
    int localb, shift, segoff;
    if (b < B_W0) {
        W = W0; localb = b; shift = 11; segoff = 0;
    } else if (b < B_W0 + B_W1) {
        W = W1; localb = b - B_W0; shift = 12; segoff = SEGS_PER_LAYER;
    } else {
        W = W2; localb = b - (B_W0 + B_W1); shift = 12;
        segoff = 2 * SEGS_PER_LAYER;
    }
    const ulonglong2* base = (const ulonglong2*)W;
    int e0 = localb * 2048 + threadIdx.x;   // ull2 index, stride 256 per k

    ulonglong2 v[8];
#pragma unroll
    for (int k = 0; k < 8; k++) v[k] = __ldg(&base[e0 + k * 256]);

    u64 any = 0ull;
#pragma unroll
    for (int k = 0; k < 8; k++) any |= v[k].x | v[k].y;
    if (!any) return;   // ~78% of threads exit here

#pragma unroll
    for (int k = 0; k < 8; k++) {
        u64 wx = v[k].x, wy = v[k].y;
        if (wx | wy) {
            int fbase = (e0 + k * 256) * 4;   // float index of v[k].x low
            if (wx) {
                u32 lo = (u32)wx, hi = (u32)(wx >> 32);
                if (lo) emit_hit(segoff, shift, fbase + 0, lo);
                if (hi) emit_hit(segoff, shift, fbase + 1, hi);
            }
            if (wy) {
                u32 lo = (u32)wy, hi = (u32)(wy >> 32);
                if (lo) emit_hit(segoff, shift, fbase + 2, lo);
                if (hi) emit_hit(segoff, shift, fbase + 3, hi);
            }
        }
    }
}

// -------------------------------------------------------------------------
// Fire: warp per neuron. Lane L owns batches L and L+32. Loops the <=32
// hits of each segment with warp-uniform loads (hit entry and act mask are
// L1 broadcasts), exact integer counts, ballots -> fired mask, plain store.
// Hit order is atomic-dependent but integer addition commutes -> exact.
// -------------------------------------------------------------------------
__global__ __launch_bounds__(256) void fire_kernel(
    const u64* __restrict__ act, int segoff, u64* __restrict__ fired) {
    int h = (blockIdx.x * blockDim.x + threadIdx.x) >> 5;
    int lane = threadIdx.x & 31;
    if (h >= HN) return;

    u64 fm = 0ull;
#pragma unroll
    for (int s = 0; s < 2; s++) {
        int seg = segoff + h * 2 + s;
        int n = (int)g_cnt[seg];
        if (n > MAXH) n = MAXH;
        const u32* hp = &g_hits[seg * MAXH];
        int c0 = 0, c1 = 0;
        for (int k = 0; k < n; k++) {
            u32 e = __ldg(&hp[k]);                       // uniform
            u64 m = __ldg(&act[e & 0x7fffffffu]);        // uniform
            int sgn = ((int)e < 0) ? -1 : 1;
            c0 += sgn * (int)((m >> lane) & 1ull);
            c1 += sgn * (int)((m >> (lane + 32)) & 1ull);
        }
        unsigned lo = __ballot_sync(0xffffffffu, c0 >= THETA);
        unsigned hi = __ballot_sync(0xffffffffu, c1 >= THETA);
        fm |= ((u64)hi << 32) | (u64)lo;
    }
    if (lane == 0) fired[h] = fm;
}

// -------------------------------------------------------------------------
// Output stage 1: partial sums over (l,h) slices.
// -------------------------------------------------------------------------
__global__ __launch_bounds__(640) void out_partial_kernel(
    const float* __restrict__ oW,
    const u64* __restrict__ fired,
    float* __restrict__ part) {
    int t = threadIdx.x;          // 0..639
    int b = t & 63;
    int c = t >> 6;
    int start = blockIdx.x * LH_PER_BLOCK;
    float acc = 0.0f;
#pragma unroll 16
    for (int i = 0; i < LH_PER_BLOCK; i++) {
        int lh = start + i;       // flat l*H + h
        u64 m = __ldg(&fired[lh]);
        float w = __ldg(&oW[lh * CC + c]);
        acc += w * (float)((m >> b) & 1ull);
    }
    part[blockIdx.x * (BB * CC) + t] = acc;
}

// Output stage 2: deterministic fixed-order reduction of partials.
__global__ void out_reduce_kernel(const float* __restrict__ part,
                                  float* __restrict__ out) {
    int t = threadIdx.x;
    if (t >= BB * CC) return;
    float s = 0.0f;
#pragma unroll
    for (int k = 0; k < OUT_BLOCKS; k++) s += part[k * (BB * CC) + t];
    int b = t & 63;
    int c = t >> 6;
    out[b * CC + c] = s;
}

// -------------------------------------------------------------------------
extern "C" void kernel_launch(void* const* d_in, const int* in_sizes, int n_in,
                              void* d_out, int out_size) {
    const float* x  = (const float*)d_in[0];
    const float* W0 = (const float*)d_in[1];
    const float* W1 = (const float*)d_in[2];
    const float* W2 = (const float*)d_in[3];
    const float* oW = (const float*)d_in[4];
    float* out = (float*)d_out;

    u64* act = nullptr;
    u64* fired = nullptr;
    float* part = nullptr;
    cudaGetSymbolAddress((void**)&act, g_act);
    cudaGetSymbolAddress((void**)&fired, g_fired);
    cudaGetSymbolAddress((void**)&part, g_part);

    zero_cnt_kernel<<<(TOT_SEGS + 255) / 256, 256>>>();
    encode_kernel<<<(P0 + 255) / 256, 256>>>(x);
    extract_kernel<<<B_W0 + B_W1 + B_W2, 256>>>(W0, W1, W2);
    fire_kernel<<<512, 256>>>(act, 0, fired);
    fire_kernel<<<512, 256>>>(fired, SEGS_PER_LAYER, fired + HN);
    fire_kernel<<<512, 256>>>(fired + HN, 2 * SEGS_PER_LAYER, fired + 2 * HN);
    out_partial_kernel<<<OUT_BLOCKS, BB * CC>>>(oW, fired, part);
    out_reduce_kernel<<<1, BB * CC>>>(part, out);
}

// round 8
// speedup vs baseline: 1.8195x; 1.8195x over previous
#include <cuda_runtime.h>
#include <cstdint>

typedef unsigned long long u64;
typedef unsigned int u32;

#define NUM_BITS 16
#define THETA 8
#define HN 4096
#define FF 128
#define CC 10
#define BB 64
#define P0 2048                      // F*NUM_BITS
#define SEGS_PER_LAYER (2 * HN)      // 8192
#define TOT_SEGS (3 * SEGS_PER_LAYER)
#define MAXH 32

#define OUT_BLOCKS 192
#define LH_TOTAL (3 * HN)                      // 12288
#define LH_PER_BLOCK (LH_TOTAL / OUT_BLOCKS)   // 64

// Scratch (device globals: no allocation allowed in kernel_launch)
__device__ u64 g_act[P0];                 // layer-0 input masks
__device__ u64 g_fired[3 * HN];           // per-layer fired masks
__device__ u32 g_cnt[TOT_SEGS];           // hits per segment (<= 32)
__device__ u32 g_hits[TOT_SEGS * MAXH];   // p | signbit<<31
__device__ float g_part[OUT_BLOCKS * BB * CC];

// -------------------------------------------------------------------------
// Encode: x[B,F] -> g_act[p], p = f*16 + t, bit b = (x[b,f] >= (t+1)/17)
// -------------------------------------------------------------------------
__global__ void encode_kernel(const float* __restrict__ x) {
    int p = blockIdx.x * blockDim.x + threadIdx.x;
    if (p >= P0) return;
    int f = p >> 4;
    int t = p & 15;
    float thr = (float)(t + 1) / (float)(NUM_BITS + 1);   // division, as ref
    u64 m = 0ull;
#pragma unroll
    for (int b = 0; b < BB; b++) {
        float v = __ldg(&x[b * FF + f]);
        m |= ((u64)(v >= thr)) << b;
    }
    g_act[p] = m;
}

// -------------------------------------------------------------------------
// Extract: one warp per SEGMENT. Streams the P-float row with 8-deep
// batched uint4 loads. Per step, 4 component ballots assign each nonzero
// an ordered slot (deterministic, no atomics); plain STG into the segment's
// hit list; warp-uniform running count; lane0 stores g_cnt at the end.
// -------------------------------------------------------------------------
template <int P>
__global__ __launch_bounds__(256) void extract_kernel(
    const float* __restrict__ W, int segbase) {
    int seg = (blockIdx.x * blockDim.x + threadIdx.x) >> 5;  // 0..8191
    int lane = threadIdx.x & 31;
    u32 ltmask = (1u << lane) - 1u;

    const uint4* row = (const uint4*)(W + (size_t)seg * (size_t)P);
    u32* hp = &g_hits[(size_t)(segbase + seg) * MAXH];
    int base = 0;

    constexpr int NS = P / 128;       // uint4 steps per lane: 16 or 32
#pragma unroll
    for (int pass = 0; pass < NS / 8; pass++) {
        uint4 v[8];
#pragma unroll
        for (int k = 0; k < 8; k++)
            v[k] = __ldg(&row[(pass * 8 + k) * 32 + lane]);

#pragma unroll
        for (int k = 0; k < 8; k++) {
            int step = pass * 8 + k;
            uint4 w = v[k];
            u32 b0 = __ballot_sync(0xffffffffu, w.x != 0u);
            u32 b1 = __ballot_sync(0xffffffffu, w.y != 0u);
            u32 b2 = __ballot_sync(0xffffffffu, w.z != 0u);
            u32 b3 = __ballot_sync(0xffffffffu, w.w != 0u);
            if (b0 | b1 | b2 | b3) {
                int p = (step * 32 + lane) * 4;
                int o0 = base;
                int o1 = o0 + __popc(b0);
                int o2 = o1 + __popc(b1);
                int o3 = o2 + __popc(b2);
                if (w.x) {
                    int s = o0 + __popc(b0 & ltmask);
                    if (s < MAXH) hp[s] = (u32)p | (w.x & 0x80000000u);
                }
                if (w.y) {
                    int s = o1 + __popc(b1 & ltmask);
                    if (s < MAXH) hp[s] = (u32)(p + 1) | (w.y & 0x80000000u);
                }
                if (w.z) {
                    int s = o2 + __popc(b2 & ltmask);
                    if (s < MAXH) hp[s] = (u32)(p + 2) | (w.z & 0x80000000u);
                }
                if (w.w) {
                    int s = o3 + __popc(b3 & ltmask);
                    if (s < MAXH) hp[s] = (u32)(p + 3) | (w.w & 0x80000000u);
                }
                base = o3 + __popc(b3);
            }
        }
    }
    if (lane == 0)
        g_cnt[segbase + seg] = (u32)(base > MAXH ? MAXH : base);
}

// -------------------------------------------------------------------------
// Fire: one warp per NEURON. Lane k loads hit k of both segments and the
// corresponding act masks (all parallel, one latency exposure). Then a
// register-only shfl loop: iteration k broadcasts hit k's mask+sign; each
// lane updates exact integer counts for its two owned batches (lane, lane+32)
// for both segments. 2 ballots -> fired mask, plain store. Deterministic.
// -------------------------------------------------------------------------
__global__ __launch_bounds__(256) void fire_kernel(
    const u64* __restrict__ act, int segbase, u64* __restrict__ fired) {
    int h = (blockIdx.x * blockDim.x + threadIdx.x) >> 5;
    int lane = threadIdx.x & 31;
    if (h >= HN) return;

    int seg0 = segbase + 2 * h;
    int n0 = (int)g_cnt[seg0];
    int n1 = (int)g_cnt[seg0 + 1];

    u64 m0 = 0ull, m1 = 0ull;
    int s0 = 0, s1 = 0;
    if (lane < n0) {
        u32 e = __ldg(&g_hits[(size_t)seg0 * MAXH + lane]);
        m0 = __ldg(&act[e & 0x7fffffffu]);
        s0 = ((int)e < 0) ? -1 : 1;
    }
    if (lane < n1) {
        u32 e = __ldg(&g_hits[(size_t)(seg0 + 1) * MAXH + lane]);
        m1 = __ldg(&act[e & 0x7fffffffu]);
        s1 = ((int)e < 0) ? -1 : 1;
    }

    int c0 = 0, c1 = 0, d0 = 0, d1 = 0;
#pragma unroll 8
    for (int k = 0; k < 32; k++) {
        u64 M0 = __shfl_sync(0xffffffffu, m0, k);
        int S0 = __shfl_sync(0xffffffffu, s0, k);
        c0 += S0 * (int)((M0 >> lane) & 1ull);
        c1 += S0 * (int)((M0 >> (lane + 32)) & 1ull);
        u64 M1 = __shfl_sync(0xffffffffu, m1, k);
        int S1 = __shfl_sync(0xffffffffu, s1, k);
        d0 += S1 * (int)((M1 >> lane) & 1ull);
        d1 += S1 * (int)((M1 >> (lane + 32)) & 1ull);
    }

    u32 lo = __ballot_sync(0xffffffffu, (c0 >= THETA) || (d0 >= THETA));
    u32 hi = __ballot_sync(0xffffffffu, (c1 >= THETA) || (d1 >= THETA));
    if (lane == 0) fired[h] = ((u64)hi << 32) | (u64)lo;
}

// -------------------------------------------------------------------------
// Output stage 1: partial sums over (l,h) slices.
// -------------------------------------------------------------------------
__global__ __launch_bounds__(640) void out_partial_kernel(
    const float* __restrict__ oW,
    const u64* __restrict__ fired,
    float* __restrict__ part) {
    int t = threadIdx.x;          // 0..639
    int b = t & 63;
    int c = t >> 6;
    int start = blockIdx.x * LH_PER_BLOCK;
    float acc = 0.0f;
#pragma unroll 16
    for (int i = 0; i < LH_PER_BLOCK; i++) {
        int lh = start + i;       // flat l*H + h
        u64 m = __ldg(&fired[lh]);
        float w = __ldg(&oW[lh * CC + c]);
        acc += w * (float)((m >> b) & 1ull);
    }
    part[blockIdx.x * (BB * CC) + t] = acc;
}

// Output stage 2: deterministic fixed-order reduction of partials.
__global__ void out_reduce_kernel(const float* __restrict__ part,
                                  float* __restrict__ out) {
    int t = threadIdx.x;
    if (t >= BB * CC) return;
    float s = 0.0f;
#pragma unroll
    for (int k = 0; k < OUT_BLOCKS; k++) s += part[k * (BB * CC) + t];
    int b = t & 63;
    int c = t >> 6;
    out[b * CC + c] = s;
}

// -------------------------------------------------------------------------
extern "C" void kernel_launch(void* const* d_in, const int* in_sizes, int n_in,
                              void* d_out, int out_size) {
    const float* x  = (const float*)d_in[0];
    const float* W0 = (const float*)d_in[1];
    const float* W1 = (const float*)d_in[2];
    const float* W2 = (const float*)d_in[3];
    const float* oW = (const float*)d_in[4];
    float* out = (float*)d_out;

    u64* act = nullptr;
    u64* fired = nullptr;
    float* part = nullptr;
    cudaGetSymbolAddress((void**)&act, g_act);
    cudaGetSymbolAddress((void**)&fired, g_fired);
    cudaGetSymbolAddress((void**)&part, g_part);

    encode_kernel<<<(P0 + 255) / 256, 256>>>(x);
    // warp per segment: 8192 warps per layer = 1024 blocks * 8 warps
    extract_kernel<P0><<<1024, 256>>>(W0, 0);
    extract_kernel<HN><<<1024, 256>>>(W1, SEGS_PER_LAYER);
    extract_kernel<HN><<<1024, 256>>>(W2, 2 * SEGS_PER_LAYER);
    // warp per neuron: 4096 warps = 512 blocks * 8 warps
    fire_kernel<<<512, 256>>>(act, 0, fired);
    fire_kernel<<<512, 256>>>(fired, SEGS_PER_LAYER, fired + HN);
    fire_kernel<<<512, 256>>>(fired + HN, 2 * SEGS_PER_LAYER, fired + 2 * HN);
    out_partial_kernel<<<OUT_BLOCKS, BB * CC>>>(oW, fired, part);
    out_reduce_kernel<<<1, BB * CC>>>(part, out);
}

// round 9
// speedup vs baseline: 2.0969x; 1.1525x over previous
#include <cuda_runtime.h>
#include <cstdint>

typedef unsigned long long u64;
typedef unsigned int u32;

#define NUM_BITS 16
#define THETA 8
#define HN 4096
#define FF 128
#define CC 10
#define BB 64
#define P0 2048                      // F*NUM_BITS
#define SEGS_PER_LAYER (2 * HN)      // 8192
#define TOT_SEGS (3 * SEGS_PER_LAYER)
#define MAXH 32

#define OUT_BLOCKS 192
#define LH_TOTAL (3 * HN)                      // 12288
#define LH_PER_BLOCK (LH_TOTAL / OUT_BLOCKS)   // 64

// Scratch (device globals: no allocation allowed in kernel_launch)
__device__ u64 g_act[P0];                 // layer-0 input masks
__device__ u64 g_fired[3 * HN];           // per-layer fired masks
__device__ u32 g_cnt[TOT_SEGS];           // hits per segment (<= 32)
__device__ u32 g_hits[TOT_SEGS * MAXH];   // p | signbit<<31
__device__ float g_part[OUT_BLOCKS * BB * CC];

// -------------------------------------------------------------------------
// Encode: x[B,F] -> g_act[p], p = f*16 + t, bit b = (x[b,f] >= (t+1)/17)
// -------------------------------------------------------------------------
__global__ void encode_kernel(const float* __restrict__ x) {
    int p = blockIdx.x * blockDim.x + threadIdx.x;
    if (p >= P0) return;
    int f = p >> 4;
    int t = p & 15;
    float thr = (float)(t + 1) / (float)(NUM_BITS + 1);
    u64 m = 0ull;
#pragma unroll
    for (int b = 0; b < BB; b++) {
        float v = __ldg(&x[b * FF + f]);
        m |= ((u64)(v >= thr)) << b;
    }
    g_act[p] = m;
}

// -------------------------------------------------------------------------
// Extract: one warp per SEGMENT. Streams the P-float row with 8-deep
// batched uint4 loads. Per step, 4 component ballots assign each nonzero
// an ordered slot (deterministic, no atomics); plain STG into the segment's
// hit list; warp-uniform running count; lane0 stores g_cnt at the end.
// -------------------------------------------------------------------------
template <int P>
__global__ __launch_bounds__(256) void extract_kernel(
    const float* __restrict__ W, int segbase) {
    int seg = (blockIdx.x * blockDim.x + threadIdx.x) >> 5;  // 0..8191
    int lane = threadIdx.x & 31;
    u32 ltmask = (1u << lane) - 1u;

    const uint4* row = (const uint4*)(W + (size_t)seg * (size_t)P);
    u32* hp = &g_hits[(size_t)(segbase + seg) * MAXH];
    int base = 0;

    constexpr int NS = P / 128;       // uint4 steps per lane: 16 or 32
#pragma unroll
    for (int pass = 0; pass < NS / 8; pass++) {
        uint4 v[8];
#pragma unroll
        for (int k = 0; k < 8; k++)
            v[k] = __ldg(&row[(pass * 8 + k) * 32 + lane]);

#pragma unroll
        for (int k = 0; k < 8; k++) {
            int step = pass * 8 + k;
            uint4 w = v[k];
            u32 b0 = __ballot_sync(0xffffffffu, w.x != 0u);
            u32 b1 = __ballot_sync(0xffffffffu, w.y != 0u);
            u32 b2 = __ballot_sync(0xffffffffu, w.z != 0u);
            u32 b3 = __ballot_sync(0xffffffffu, w.w != 0u);
            if (b0 | b1 | b2 | b3) {
                int p = (step * 32 + lane) * 4;
                int o0 = base;
                int o1 = o0 + __popc(b0);
                int o2 = o1 + __popc(b1);
                int o3 = o2 + __popc(b2);
                if (w.x) {
                    int s = o0 + __popc(b0 & ltmask);
                    if (s < MAXH) hp[s] = (u32)p | (w.x & 0x80000000u);
                }
                if (w.y) {
                    int s = o1 + __popc(b1 & ltmask);
                    if (s < MAXH) hp[s] = (u32)(p + 1) | (w.y & 0x80000000u);
                }
                if (w.z) {
                    int s = o2 + __popc(b2 & ltmask);
                    if (s < MAXH) hp[s] = (u32)(p + 2) | (w.z & 0x80000000u);
                }
                if (w.w) {
                    int s = o3 + __popc(b3 & ltmask);
                    if (s < MAXH) hp[s] = (u32)(p + 3) | (w.w & 0x80000000u);
                }
                base = o3 + __popc(b3);
            }
        }
    }
    if (lane == 0)
        g_cnt[segbase + seg] = (u32)(base > MAXH ? MAXH : base);
}

// -------------------------------------------------------------------------
// Fire: one warp per NEURON. Lane k loads hit k of both segments and the
// corresponding act masks (parallel, one latency exposure). Register-only
// shfl loop accumulates exact integer counts for each lane's two owned
// batches; 2 ballots -> fired mask, plain store. Deterministic.
// -------------------------------------------------------------------------
__global__ __launch_bounds__(256) void fire_kernel(
    const u64* __restrict__ act, int segbase, u64* __restrict__ fired) {
    int h = (blockIdx.x * blockDim.x + threadIdx.x) >> 5;
    int lane = threadIdx.x & 31;
    if (h >= HN) return;

    int seg0 = segbase + 2 * h;
    int n0 = (int)g_cnt[seg0];
    int n1 = (int)g_cnt[seg0 + 1];

    u64 m0 = 0ull, m1 = 0ull;
    int s0 = 0, s1 = 0;
    if (lane < n0) {
        u32 e = __ldg(&g_hits[(size_t)seg0 * MAXH + lane]);
        m0 = __ldg(&act[e & 0x7fffffffu]);
        s0 = ((int)e < 0) ? -1 : 1;
    }
    if (lane < n1) {
        u32 e = __ldg(&g_hits[(size_t)(seg0 + 1) * MAXH + lane]);
        m1 = __ldg(&act[e & 0x7fffffffu]);
        s1 = ((int)e < 0) ? -1 : 1;
    }

    int c0 = 0, c1 = 0, d0 = 0, d1 = 0;
#pragma unroll 8
    for (int k = 0; k < 32; k++) {
        u64 M0 = __shfl_sync(0xffffffffu, m0, k);
        int S0 = __shfl_sync(0xffffffffu, s0, k);
        c0 += S0 * (int)((M0 >> lane) & 1ull);
        c1 += S0 * (int)((M0 >> (lane + 32)) & 1ull);
        u64 M1 = __shfl_sync(0xffffffffu, m1, k);
        int S1 = __shfl_sync(0xffffffffu, s1, k);
        d0 += S1 * (int)((M1 >> lane) & 1ull);
        d1 += S1 * (int)((M1 >> (lane + 32)) & 1ull);
    }

    u32 lo = __ballot_sync(0xffffffffu, (c0 >= THETA) || (d0 >= THETA));
    u32 hi = __ballot_sync(0xffffffffu, (c1 >= THETA) || (d1 >= THETA));
    if (lane == 0) fired[h] = ((u64)hi << 32) | (u64)lo;
}

// -------------------------------------------------------------------------
// Output stage 1: partial sums over (l,h) slices.
// -------------------------------------------------------------------------
__global__ __launch_bounds__(640) void out_partial_kernel(
    const float* __restrict__ oW,
    const u64* __restrict__ fired,
    float* __restrict__ part) {
    int t = threadIdx.x;          // 0..639
    int b = t & 63;
    int c = t >> 6;
    int start = blockIdx.x * LH_PER_BLOCK;
    float acc = 0.0f;
#pragma unroll 16
    for (int i = 0; i < LH_PER_BLOCK; i++) {
        int lh = start + i;       // flat l*H + h
        u64 m = __ldg(&fired[lh]);
        float w = __ldg(&oW[lh * CC + c]);
        acc += w * (float)((m >> b) & 1ull);
    }
    part[blockIdx.x * (BB * CC) + t] = acc;
}

// Output stage 2: deterministic fixed-order reduction of partials.
__global__ void out_reduce_kernel(const float* __restrict__ part,
                                  float* __restrict__ out) {
    int t = threadIdx.x;
    if (t >= BB * CC) return;
    float s = 0.0f;
#pragma unroll
    for (int k = 0; k < OUT_BLOCKS; k++) s += part[k * (BB * CC) + t];
    int b = t & 63;
    int c = t >> 6;
    out[b * CC + c] = s;
}

// -------------------------------------------------------------------------
// Launch: two-stream schedule captured into the graph.
//   s0: encode -> extract0 -> fire0 -> [e1] fire1 -> [e2] fire2 -> out
//   s1: (fork)   extract1 -> e1 -> extract2 -> e2
// fire/out kernels (latency-bound, ~0 DRAM) hide under s1's 256MB stream.
// -------------------------------------------------------------------------
extern "C" void kernel_launch(void* const* d_in, const int* in_sizes, int n_in,
                              void* d_out, int out_size) {
    const float* x  = (const float*)d_in[0];
    const float* W0 = (const float*)d_in[1];
    const float* W1 = (const float*)d_in[2];
    const float* W2 = (const float*)d_in[3];
    const float* oW = (const float*)d_in[4];
    float* out = (float*)d_out;

    u64* act = nullptr;
    u64* fired = nullptr;
    float* part = nullptr;
    cudaGetSymbolAddress((void**)&act, g_act);
    cudaGetSymbolAddress((void**)&fired, g_fired);
    cudaGetSymbolAddress((void**)&part, g_part);

    cudaStream_t s1;
    cudaStreamCreateWithFlags(&s1, cudaStreamNonBlocking);
    cudaEvent_t eFork, e1, e2;
    cudaEventCreateWithFlags(&eFork, cudaEventDisableTiming);
    cudaEventCreateWithFlags(&e1, cudaEventDisableTiming);
    cudaEventCreateWithFlags(&e2, cudaEventDisableTiming);

    encode_kernel<<<(P0 + 255) / 256, 256>>>(x);

    // fork side stream into the capture
    cudaEventRecord(eFork, 0);
    cudaStreamWaitEvent(s1, eFork, 0);

    // s0: layer-0 weights; s1: layer-1/2 weights
    extract_kernel<P0><<<1024, 256>>>(W0, 0);
    extract_kernel<HN><<<1024, 256, 0, s1>>>(W1, SEGS_PER_LAYER);
    cudaEventRecord(e1, s1);
    extract_kernel<HN><<<1024, 256, 0, s1>>>(W2, 2 * SEGS_PER_LAYER);
    cudaEventRecord(e2, s1);

    // s0: fire chain overlapping s1's extracts
    fire_kernel<<<512, 256>>>(act, 0, fired);
    cudaStreamWaitEvent(0, e1, 0);
    fire_kernel<<<512, 256>>>(fired, SEGS_PER_LAYER, fired + HN);
    cudaStreamWaitEvent(0, e2, 0);   // join: s1 fully merged back
    fire_kernel<<<512, 256>>>(fired + HN, 2 * SEGS_PER_LAYER, fired + 2 * HN);

    out_partial_kernel<<<OUT_BLOCKS, BB * CC>>>(oW, fired, part);
    out_reduce_kernel<<<1, BB * CC>>>(part, out);
}